// round 14
// baseline (speedup 1.0000x reference)
#include <cuda_runtime.h>
#include <math.h>
#include <stdint.h>

// ---------------- problem constants ----------------
#define BB   16
#define TTRG 64
#define TT   64
#define SS   49
#define DD   512
#define DFF  2048
#define HH   8
#define NTOK_X    (BB*TTRG)          // 1024
#define NTOK_VFT  (BB*TT*SS)         // 50176
#define NTOK_SOUT (BB*TT*TTRG)       // 65536

// ---------------- scratch ----------------
__device__ float g_cur [NTOK_X*DD];
__device__ float g_lnA [NTOK_X*DD];
__device__ float g_lnB [NTOK_X*DD];
__device__ float g_lnC [NTOK_X*DD];
__device__ float g_qA  [NTOK_X*DD];
__device__ float g_qB  [NTOK_X*DD];
__device__ float g_ks  [2048*DD];
__device__ float g_vs  [2048*DD];
__device__ float g_abA [NTOK_X*DD];
__device__ float g_abB [NTOK_X*DD];
__device__ float g_ts  [NTOK_X*DD];
__device__ float g_st  [NTOK_X*DD];
__device__ float g_ffhA[NTOK_X*DFF];
__device__ float g_ffhB[NTOK_X*DFF];
__device__ float g_big0[NTOK_SOUT*DD];
__device__ float g_big1[NTOK_SOUT*DD];
__device__ float g_big2[NTOK_SOUT*DD];   // head: ao_A; tail @26M: mha1-3 KV
__device__ float g_big3[NTOK_SOUT*DD];   // chain A scratch
__device__ float g_big4[NTOK_SOUT*DD];
__device__ float g_big5[NTOK_SOUT*DD];
__device__ float g_big6[NTOK_SOUT*DD];
__device__ float g_big7[NTOK_SOUT*DD];   // chain B scratch
__device__ int   g_map_perm[NTOK_VFT];
__device__ int   g_map_pt  [NTOK_VFT];
__device__ int   g_map_ps  [NTOK_SOUT];

// ---------------- fused map builder ----------------
__device__ __forceinline__ int swap_map(int m, int Bd, int Cd) {
    int c = m % Cd;
    int b = (m / Cd) % Bd;
    int a = m / (Cd*Bd);
    return (a*Cd + c)*Bd + b;
}
__global__ void build_maps_kernel() {
    int m = blockIdx.x*256 + threadIdx.x;
    int job = blockIdx.y;
    if (job == 0)      { if (m < NTOK_VFT)  g_map_perm[m] = swap_map(m, SS, TT); }
    else if (job == 1) { if (m < NTOK_VFT)  g_map_pt[m]   = swap_map(m, TTRG, SS); }
    else               { if (m < NTOK_SOUT) g_map_ps[m]   = swap_map(m, TTRG, TT); }
}

// ---------------- block-diagonal weight builders ----------------
__global__ void build_bwk_kernel(const float* __restrict__ W, float* __restrict__ BWK) {
    int idx = blockIdx.x*256 + threadIdx.x;
    if (idx >= 512*4096) return;
    int k = idx >> 12, n = idx & 4095;
    int hk = k >> 6, c = k & 63;
    int hn = n >> 9, d = n & 511;
    BWK[idx] = (hk == hn) ? W[d*512 + hk*64 + c] : 0.0f;
}
__global__ void build_bwv_kernel(const float* __restrict__ W, float* __restrict__ BWV) {
    int idx = blockIdx.x*256 + threadIdx.x;
    if (idx >= 4096*512) return;
    int k = idx >> 9, n = idx & 511;
    int hk = k >> 9, d = k & 511;
    int hn = n >> 6, e = n & 63;
    BWV[idx] = (hk == hn) ? W[d*512 + hn*64 + e] : 0.0f;
}
__global__ void bias_compose_kernel(const float* __restrict__ b1, const float* __restrict__ W,
                                    const float* __restrict__ b2, float* __restrict__ biasv) {
    int n = blockIdx.x*8 + (threadIdx.x >> 5);
    int lane = threadIdx.x & 31;
    if (n >= 512) return;
    float s = 0.0f;
    for (int d = lane; d < 512; d += 32) s += b1[d] * W[d*512 + n];
    #pragma unroll
    for (int o = 16; o; o >>= 1) s += __shfl_xor_sync(0xffffffffu, s, o);
    if (lane == 0) biasv[n] = s + b2[n];
}

// ---------------- layernorm (D=512) ----------------
__global__ __launch_bounds__(128) void ln_kernel(const float* __restrict__ in,
                                                 const float* __restrict__ gamma,
                                                 const float* __restrict__ beta,
                                                 float* __restrict__ out) {
    int row = blockIdx.x;
    int tid = threadIdx.x;
    const float4* p = reinterpret_cast<const float4*>(in + (long)row*DD);
    float4 v = p[tid];
    float s = v.x + v.y + v.z + v.w;
    float q = v.x*v.x + v.y*v.y + v.z*v.z + v.w*v.w;
    #pragma unroll
    for (int o = 16; o; o >>= 1) {
        s += __shfl_xor_sync(0xffffffffu, s, o);
        q += __shfl_xor_sync(0xffffffffu, q, o);
    }
    __shared__ float ssum[4], ssq[4];
    int warp = tid >> 5, lane = tid & 31;
    if (lane == 0) { ssum[warp] = s; ssq[warp] = q; }
    __syncthreads();
    __shared__ float smean, sinv;
    if (tid == 0) {
        float S = ssum[0]+ssum[1]+ssum[2]+ssum[3];
        float Q = ssq[0]+ssq[1]+ssq[2]+ssq[3];
        float mean = S * (1.0f/DD);
        float var  = Q * (1.0f/DD) - mean*mean;
        float sd   = sqrtf(fmaxf(var, 0.0f));
        smean = mean;
        sinv  = 1.0f / (sd + 1e-6f);
    }
    __syncthreads();
    float mean = smean, inv = sinv;
    float4 gv = reinterpret_cast<const float4*>(gamma)[tid];
    float4 bv = reinterpret_cast<const float4*>(beta)[tid];
    float4 o;
    o.x = gv.x*(v.x-mean)*inv + bv.x;
    o.y = gv.y*(v.y-mean)*inv + bv.y;
    o.z = gv.z*(v.z-mean)*inv + bv.z;
    o.w = gv.w*(v.w-mean)*inv + bv.w;
    reinterpret_cast<float4*>(out + (long)row*DD)[tid] = o;
}

// ---------------- tf32/cp.async/ldmatrix helpers ----------------
__device__ __forceinline__ void mma_tf32(float* c, const uint32_t* a, const uint32_t* b) {
    asm volatile("mma.sync.aligned.m16n8k8.row.col.f32.tf32.tf32.f32 "
        "{%0,%1,%2,%3}, {%4,%5,%6,%7}, {%8,%9}, {%0,%1,%2,%3};"
        : "+f"(c[0]), "+f"(c[1]), "+f"(c[2]), "+f"(c[3])
        : "r"(a[0]), "r"(a[1]), "r"(a[2]), "r"(a[3]), "r"(b[0]), "r"(b[1]));
}
__device__ __forceinline__ void cp_async16(void* smem_ptr, const void* gptr) {
    uint32_t s = (uint32_t)__cvta_generic_to_shared(smem_ptr);
    asm volatile("cp.async.cg.shared.global [%0], [%1], 16;" :: "r"(s), "l"(gptr));
}
#define CP_COMMIT() asm volatile("cp.async.commit_group;")
#define CP_WAIT0()  asm volatile("cp.async.wait_group 0;")
__device__ __forceinline__ void ldsm_x4(uint32_t* r, const void* p) {
    uint32_t a = (uint32_t)__cvta_generic_to_shared(p);
    asm volatile("ldmatrix.sync.aligned.m8n8.x4.shared.b16 {%0,%1,%2,%3}, [%4];"
        : "=r"(r[0]), "=r"(r[1]), "=r"(r[2]), "=r"(r[3]) : "r"(a));
}

// ---------------- multi-chunk tf32 GEMM (128x128 tile, Kc=32) ----------------
#define TCP 136
#define ASP 36
#define BSP 72

struct GemmChunks {
    const float* w[3];
    const float* b[3];
    float*       c[3];
};

__global__ __launch_bounds__(256, 2) void sgemm_tc_kernel(
    const float* __restrict__ A, const int* __restrict__ amap,
    GemmChunks ch,
    const float* __restrict__ R, const int* __restrict__ rmap,
    int M, int N, int K, int relu)
{
    __shared__ float As[2][128][ASP];
    __shared__ float Bs[2][32][TCP];
    __shared__ int rowm[128];
    int tid = threadIdx.x;
    int ntiles = N >> 7;
    int widx = blockIdx.x / ntiles;
    int n0 = (blockIdx.x % ntiles) << 7;
    int m0 = blockIdx.y << 7;
    const float* W    = ch.w[widx];
    const float* bias = ch.b[widx];
    float*       C    = ch.c[widx];
    if (tid < 128) rowm[tid] = amap ? amap[m0 + tid] : (m0 + tid);
    __syncthreads();

    int wid = tid >> 5, lane = tid & 31;
    int warp_m = wid >> 2, warp_n = wid & 3;
    int gr = lane >> 2, gc = lane & 3;
    int lrow = lane & 15, lkq = (lane >> 4) << 2;

    int arow = tid >> 1, ak = (tid & 1) << 4;
    const float* aptr = A + (long)rowm[arow]*K + ak;
    int bk = tid >> 5, bn = (lane) << 2;
    const float* bptr = W + (long)bk*N + n0 + bn;

    float acc[4][4][4];
    #pragma unroll
    for (int i = 0; i < 4; i++)
        #pragma unroll
        for (int j = 0; j < 4; j++)
            #pragma unroll
            for (int u = 0; u < 4; u++) acc[i][j][u] = 0.0f;

    #pragma unroll
    for (int q = 0; q < 4; q++)
        cp_async16(&As[0][arow][ak + q*4], aptr + q*4);
    #pragma unroll
    for (int q = 0; q < 4; q++)
        cp_async16(&Bs[0][bk + q*8][bn], bptr + (long)(q*8)*N);
    CP_COMMIT();
    CP_WAIT0();
    __syncthreads();

    int mbase = warp_m << 6;
    int buf = 0;
    for (int k0 = 0; k0 < K; k0 += 32) {
        bool has_next = (k0 + 32) < K;
        if (has_next) {
            #pragma unroll
            for (int q = 0; q < 4; q++)
                cp_async16(&As[buf^1][arow][ak + q*4], aptr + k0 + 32 + q*4);
            #pragma unroll
            for (int q = 0; q < 4; q++)
                cp_async16(&Bs[buf^1][bk + q*8][bn], bptr + (long)(k0 + 32 + q*8)*N);
            CP_COMMIT();
        }
        uint32_t afb[2][4][4];
        #pragma unroll
        for (int mt = 0; mt < 4; mt++)
            ldsm_x4(afb[0][mt], &As[buf][mbase + (mt << 4) + lrow][lkq]);
        #pragma unroll
        for (int ks = 0; ks < 4; ks++) {
            int cur = ks & 1;
            if (ks < 3) {
                #pragma unroll
                for (int mt = 0; mt < 4; mt++)
                    ldsm_x4(afb[cur ^ 1][mt],
                            &As[buf][mbase + (mt << 4) + lrow][((ks + 1) << 3) + lkq]);
            }
            int kb = ks << 3;
            uint32_t bf[4][2];
            #pragma unroll
            for (int nt = 0; nt < 4; nt++) {
                int nb = (warp_n << 5) + (nt << 3) + gr;
                bf[nt][0] = __float_as_uint(Bs[buf][kb+gc  ][nb]);
                bf[nt][1] = __float_as_uint(Bs[buf][kb+gc+4][nb]);
            }
            #pragma unroll
            for (int mt = 0; mt < 4; mt++)
                #pragma unroll
                for (int nt = 0; nt < 4; nt++)
                    mma_tf32(acc[mt][nt], afb[cur][mt], bf[nt]);
        }
        if (has_next) CP_WAIT0();
        __syncthreads();
        buf ^= 1;
    }

    #pragma unroll
    for (int mt = 0; mt < 4; mt++) {
        #pragma unroll
        for (int half = 0; half < 2; half++) {
            int m = m0 + (warp_m << 6) + (mt << 4) + gr + (half << 3);
            long rbase = 0;
            if (R) rbase = (long)(rmap ? rmap[m] : m) * N;
            #pragma unroll
            for (int nt = 0; nt < 4; nt++) {
                int n = n0 + (warp_n << 5) + (nt << 3) + (gc << 1);
                float v0 = acc[mt][nt][half*2 + 0];
                float v1 = acc[mt][nt][half*2 + 1];
                if (bias) { v0 += bias[n]; v1 += bias[n+1]; }
                if (relu) { v0 = fmaxf(v0, 0.0f); v1 = fmaxf(v1, 0.0f); }
                if (R) {
                    float2 rv = *reinterpret_cast<const float2*>(R + rbase + n);
                    v0 += rv.x; v1 += rv.y;
                }
                *reinterpret_cast<float2*>(C + (long)m*N + n) = make_float2(v0, v1);
            }
        }
    }
}

// ---------------- 64x64-tile tf32 GEMM (128 threads, Kc=32) for small-M launches ----
__global__ __launch_bounds__(128, 4) void sgemm64_tc_kernel(
    const float* __restrict__ A, const int* __restrict__ amap,
    GemmChunks ch,
    const float* __restrict__ R, const int* __restrict__ rmap,
    int M, int N, int K, int relu)
{
    __shared__ float As[2][64][ASP];
    __shared__ float Bs[2][32][BSP];
    __shared__ int rowm[64];
    int tid = threadIdx.x;
    int ntiles = N >> 6;
    int widx = blockIdx.x / ntiles;
    int n0 = (blockIdx.x % ntiles) << 6;
    int m0 = blockIdx.y << 6;
    const float* W    = ch.w[widx];
    const float* bias = ch.b[widx];
    float*       C    = ch.c[widx];
    if (tid < 64) rowm[tid] = amap ? amap[m0 + tid] : (m0 + tid);
    __syncthreads();

    int wid = tid >> 5, lane = tid & 31;
    int warp_m = wid >> 1, warp_n = wid & 1;   // 2x2 warps, 32x32 each
    int gr = lane >> 2, gc = lane & 3;
    int lrow = lane & 15, lkq = (lane >> 4) << 2;

    int arow = tid >> 1, ak = (tid & 1) << 4;
    const float* aptr = A + (long)rowm[arow]*K + ak;
    int bk = tid >> 4, bn = (tid & 15) << 2;   // rows bk,bk+8,bk+16,bk+24
    const float* bptr = W + (long)bk*N + n0 + bn;

    float acc[2][4][4];
    #pragma unroll
    for (int i = 0; i < 2; i++)
        #pragma unroll
        for (int j = 0; j < 4; j++)
            #pragma unroll
            for (int u = 0; u < 4; u++) acc[i][j][u] = 0.0f;

    #pragma unroll
    for (int q = 0; q < 4; q++)
        cp_async16(&As[0][arow][ak + q*4], aptr + q*4);
    #pragma unroll
    for (int q = 0; q < 4; q++)
        cp_async16(&Bs[0][bk + q*8][bn], bptr + (long)(q*8)*N);
    CP_COMMIT();
    CP_WAIT0();
    __syncthreads();

    int mbase = warp_m << 5;
    int buf = 0;
    for (int k0 = 0; k0 < K; k0 += 32) {
        bool has_next = (k0 + 32) < K;
        if (has_next) {
            #pragma unroll
            for (int q = 0; q < 4; q++)
                cp_async16(&As[buf^1][arow][ak + q*4], aptr + k0 + 32 + q*4);
            #pragma unroll
            for (int q = 0; q < 4; q++)
                cp_async16(&Bs[buf^1][bk + q*8][bn], bptr + (long)(k0 + 32 + q*8)*N);
            CP_COMMIT();
        }
        uint32_t afb[2][2][4];
        #pragma unroll
        for (int mt = 0; mt < 2; mt++)
            ldsm_x4(afb[0][mt], &As[buf][mbase + (mt << 4) + lrow][lkq]);
        #pragma unroll
        for (int ks = 0; ks < 4; ks++) {
            int cur = ks & 1;
            if (ks < 3) {
                #pragma unroll
                for (int mt = 0; mt < 2; mt++)
                    ldsm_x4(afb[cur ^ 1][mt],
                            &As[buf][mbase + (mt << 4) + lrow][((ks + 1) << 3) + lkq]);
            }
            int kb = ks << 3;
            uint32_t bf[4][2];
            #pragma unroll
            for (int nt = 0; nt < 4; nt++) {
                int nb = (warp_n << 5) + (nt << 3) + gr;
                bf[nt][0] = __float_as_uint(Bs[buf][kb+gc  ][nb]);
                bf[nt][1] = __float_as_uint(Bs[buf][kb+gc+4][nb]);
            }
            #pragma unroll
            for (int mt = 0; mt < 2; mt++)
                #pragma unroll
                for (int nt = 0; nt < 4; nt++)
                    mma_tf32(acc[mt][nt], afb[cur][mt], bf[nt]);
        }
        if (has_next) CP_WAIT0();
        __syncthreads();
        buf ^= 1;
    }

    #pragma unroll
    for (int mt = 0; mt < 2; mt++) {
        #pragma unroll
        for (int half = 0; half < 2; half++) {
            int m = m0 + (warp_m << 5) + (mt << 4) + gr + (half << 3);
            long rbase = 0;
            if (R) rbase = (long)(rmap ? rmap[m] : m) * N;
            #pragma unroll
            for (int nt = 0; nt < 4; nt++) {
                int n = n0 + (warp_n << 5) + (nt << 3) + (gc << 1);
                float v0 = acc[mt][nt][half*2 + 0];
                float v1 = acc[mt][nt][half*2 + 1];
                if (bias) { v0 += bias[n]; v1 += bias[n+1]; }
                if (relu) { v0 = fmaxf(v0, 0.0f); v1 = fmaxf(v1, 0.0f); }
                if (R) {
                    float2 rv = *reinterpret_cast<const float2*>(R + rbase + n);
                    v0 += rv.x; v1 += rv.y;
                }
                *reinterpret_cast<float2*>(C + (long)m*N + n) = make_float2(v0, v1);
            }
        }
    }
}

// ---------------- tensor-core attention, Lq=64, dk=64 ----------------
__global__ __launch_bounds__(256) void attn_tc_kernel(
    const float* __restrict__ Q, const float* __restrict__ Kg,
    const float* __restrict__ Vg, float* __restrict__ O,
    int Lk, int LkPad, int q_group,
    const int* __restrict__ mask, int mask_mode, int mask_div)
{
    extern __shared__ float sm[];
    float* sQ  = sm;
    float* sKV = sm + 64*68;
    float* sS  = sKV + LkPad*68;
    int batch = blockIdx.x, h = blockIdx.y;
    int tid = threadIdx.x;
    int qbase = (batch / q_group) * 64;
    int sp = LkPad + 4;

    int wid = tid >> 5, lane = tid & 31;
    int warp_m = wid >> 2, warp_n = wid & 3;
    int gr = lane >> 2, gc = lane & 3;
    int nw  = LkPad >> 2;
    int ntn = LkPad >> 5;

    for (int c4 = tid; c4 < 64*16; c4 += 256) {
        int i = c4 >> 4, d = (c4 & 15) << 2;
        cp_async16(&sQ[i*68 + d], &Q[(long)(qbase + i)*DD + h*64 + d]);
    }
    for (int c4 = tid; c4 < Lk*16; c4 += 256) {
        int j = c4 >> 4, d = (c4 & 15) << 2;
        cp_async16(&sKV[j*68 + d], &Kg[(long)(batch*Lk + j)*DD + h*64 + d]);
    }
    CP_COMMIT();
    for (int idx = Lk*64 + tid; idx < LkPad*64; idx += 256) {
        int j = idx >> 6, d = idx & 63;
        sKV[j*68 + d] = 0.0f;
    }
    CP_WAIT0();
    __syncthreads();

    {
        float acc[2][4][4];
        #pragma unroll
        for (int mt = 0; mt < 2; mt++)
            #pragma unroll
            for (int nt = 0; nt < 4; nt++)
                #pragma unroll
                for (int u = 0; u < 4; u++) acc[mt][nt][u] = 0.0f;

        for (int kb = 0; kb < 64; kb += 8) {
            uint32_t af[2][4];
            #pragma unroll
            for (int mt = 0; mt < 2; mt++) {
                int mr = warp_m*32 + mt*16 + gr;
                af[mt][0] = __float_as_uint(sQ[mr*68 + kb+gc]);
                af[mt][1] = __float_as_uint(sQ[(mr+8)*68 + kb+gc]);
                af[mt][2] = __float_as_uint(sQ[mr*68 + kb+gc+4]);
                af[mt][3] = __float_as_uint(sQ[(mr+8)*68 + kb+gc+4]);
            }
            for (int nt = 0; nt < ntn; nt++) {
                int nc = warp_n*nw + nt*8 + gr;
                uint32_t bf[2];
                bf[0] = __float_as_uint(sKV[nc*68 + kb+gc]);
                bf[1] = __float_as_uint(sKV[nc*68 + kb+gc+4]);
                mma_tf32(acc[0][nt], af[0], bf);
                mma_tf32(acc[1][nt], af[1], bf);
            }
        }
        #pragma unroll
        for (int mt = 0; mt < 2; mt++)
            for (int nt = 0; nt < ntn; nt++) {
                int row = warp_m*32 + mt*16 + gr;
                int col = warp_n*nw + nt*8 + (gc << 1);
                sS[row*sp + col]       = acc[mt][nt][0]*0.125f;
                sS[row*sp + col + 1]   = acc[mt][nt][1]*0.125f;
                sS[(row+8)*sp + col]   = acc[mt][nt][2]*0.125f;
                sS[(row+8)*sp + col+1] = acc[mt][nt][3]*0.125f;
            }
    }
    __syncthreads();

    for (int c4 = tid; c4 < Lk*16; c4 += 256) {
        int j = c4 >> 4, d = (c4 & 15) << 2;
        cp_async16(&sKV[j*68 + d], &Vg[(long)(batch*Lk + j)*DD + h*64 + d]);
    }
    CP_COMMIT();

    for (int i = wid; i < 64; i += 8) {
        float mx = -3.4e38f;
        for (int j = lane; j < Lk; j += 32) {
            float v = sS[i*sp + j];
            bool dead = false;
            if (mask_mode == 1) dead = (mask[(long)(batch*64 + i)*Lk + j] == 0);
            else if (mask_mode == 2) dead = (mask[(batch/mask_div)*Lk + j] == 0);
            if (dead) { v = -1e9f; sS[i*sp + j] = v; }
            mx = fmaxf(mx, v);
        }
        #pragma unroll
        for (int o = 16; o; o >>= 1) mx = fmaxf(mx, __shfl_xor_sync(0xffffffffu, mx, o));
        float sum = 0.0f;
        for (int j = lane; j < Lk; j += 32) {
            float e = __expf(sS[i*sp + j] - mx);
            sS[i*sp + j] = e;
            sum += e;
        }
        #pragma unroll
        for (int o = 16; o; o >>= 1) sum += __shfl_xor_sync(0xffffffffu, sum, o);
        float inv = 1.0f / sum;
        for (int j = lane; j < Lk; j += 32) sS[i*sp + j] *= inv;
        for (int j = Lk + lane; j < LkPad; j += 32) sS[i*sp + j] = 0.0f;
    }
    CP_WAIT0();
    __syncthreads();

    {
        float acc[2][2][4];
        #pragma unroll
        for (int mt = 0; mt < 2; mt++)
            #pragma unroll
            for (int nt = 0; nt < 2; nt++)
                #pragma unroll
                for (int u = 0; u < 4; u++) acc[mt][nt][u] = 0.0f;

        for (int kb = 0; kb < LkPad; kb += 8) {
            uint32_t af[2][4];
            #pragma unroll
            for (int mt = 0; mt < 2; mt++) {
                int mr = warp_m*32 + mt*16 + gr;
                af[mt][0] = __float_as_uint(sS[mr*sp + kb+gc]);
                af[mt][1] = __float_as_uint(sS[(mr+8)*sp + kb+gc]);
                af[mt][2] = __float_as_uint(sS[mr*sp + kb+gc+4]);
                af[mt][3] = __float_as_uint(sS[(mr+8)*sp + kb+gc+4]);
            }
            #pragma unroll
            for (int nt = 0; nt < 2; nt++) {
                int nc = warp_n*16 + nt*8 + gr;
                uint32_t bf[2];
                int k0r = kb+gc, k1r = kb+gc+4;
                bf[0] = (k0r < Lk) ? __float_as_uint(sKV[k0r*68 + nc]) : 0u;
                bf[1] = (k1r < Lk) ? __float_as_uint(sKV[k1r*68 + nc]) : 0u;
                mma_tf32(acc[0][nt], af[0], bf);
                mma_tf32(acc[1][nt], af[1], bf);
            }
        }
        #pragma unroll
        for (int mt = 0; mt < 2; mt++)
            #pragma unroll
            for (int nt = 0; nt < 2; nt++) {
                int i = warp_m*32 + mt*16 + gr;
                int d = warp_n*16 + nt*8 + (gc << 1);
                long base = (long)(batch*64 + i)*DD + h*64 + d;
                *reinterpret_cast<float2*>(O + base) =
                    make_float2(acc[mt][nt][0], acc[mt][nt][1]);
                *reinterpret_cast<float2*>(O + base + 8*DD) =
                    make_float2(acc[mt][nt][2], acc[mt][nt][3]);
            }
    }
}

// ---------------- wide Lq=1 attention over RAW rows ----------------
__global__ __launch_bounds__(256) void attn_wide_kernel(
    const float* __restrict__ QT, const float* __restrict__ SRC,
    const int* __restrict__ map, float* __restrict__ SB,
    int Lk, const int* __restrict__ mask, int mask_mode, int mask_div)
{
    __shared__ float qt8[8*512];
    __shared__ float krow[8][516];
    __shared__ float sS[8][72];
    __shared__ int   rows[64];
    int q = blockIdx.x;
    int tid = threadIdx.x;
    int h = tid >> 5, lane = tid & 31;

    for (int i = tid; i < 4096; i += 256) qt8[i] = QT[(long)q*4096 + i];
    if (tid < Lk) rows[tid] = map[q*Lk + tid];
    __syncthreads();

    for (int jt = 0; jt < Lk; jt += 8) {
        int nj = min(8, Lk - jt);
        for (int idx = tid; idx < nj*512; idx += 256) {
            int j = idx >> 9, d = idx & 511;
            krow[j][d] = SRC[(long)rows[jt + j]*512 + d];
        }
        __syncthreads();
        for (int j = 0; j < nj; j++) {
            float s = 0.0f;
            #pragma unroll
            for (int i = 0; i < 16; i++)
                s += qt8[h*512 + i*32 + lane] * krow[j][i*32 + lane];
            #pragma unroll
            for (int o = 16; o; o >>= 1) s += __shfl_xor_sync(0xffffffffu, s, o);
            if (lane == 0) sS[h][jt + j] = s * 0.125f;
        }
        __syncthreads();
    }

    {
        float mx = -3.4e38f;
        for (int j = lane; j < Lk; j += 32) {
            float v = sS[h][j];
            if (mask_mode == 2 && mask[(q/mask_div)*Lk + j] == 0) { v = -1e9f; sS[h][j] = v; }
            mx = fmaxf(mx, v);
        }
        #pragma unroll
        for (int o = 16; o; o >>= 1) mx = fmaxf(mx, __shfl_xor_sync(0xffffffffu, mx, o));
        float sum = 0.0f;
        for (int j = lane; j < Lk; j += 32) {
            float e = __expf(sS[h][j] - mx);
            sS[h][j] = e;
            sum += e;
        }
        #pragma unroll
        for (int o = 16; o; o >>= 1) sum += __shfl_xor_sync(0xffffffffu, sum, o);
        float inv = 1.0f / sum;
        for (int j = lane; j < Lk; j += 32) sS[h][j] *= inv;
    }
    __syncthreads();

    float acc[16];
    #pragma unroll
    for (int i = 0; i < 16; i++) acc[i] = 0.0f;
    for (int jt = 0; jt < Lk; jt += 8) {
        int nj = min(8, Lk - jt);
        for (int idx = tid; idx < nj*512; idx += 256) {
            int j = idx >> 9, d = idx & 511;
            krow[j][d] = SRC[(long)rows[jt + j]*512 + d];
        }
        __syncthreads();
        for (int j = 0; j < nj; j++) {
            float p = sS[h][jt + j];
            #pragma unroll
            for (int i = 0; i < 16; i++)
                acc[i] += p * krow[j][i*32 + lane];
        }
        __syncthreads();
    }
    #pragma unroll
    for (int i = 0; i < 16; i++)
        SB[(long)q*4096 + h*512 + i*32 + lane] = acc[i];
}

// ---------------- elementwise add ----------------
__global__ void add_kernel(const float* __restrict__ a, const float* __restrict__ b,
                           float* __restrict__ c, int n) {
    int i = blockIdx.x*256 + threadIdx.x;
    if (i < n) c[i] = a[i] + b[i];
}

// ---------------- host ----------------
static float* sym_f(const void* s) { void* p = nullptr; cudaGetSymbolAddress(&p, s); return (float*)p; }
static int*   sym_i(const void* s) { void* p = nullptr; cudaGetSymbolAddress(&p, s); return (int*)p; }

extern "C" void kernel_launch(void* const* d_in, const int* in_sizes, int n_in,
                              void* d_out, int out_size) {
    const float* x    = (const float*)d_in[0];
    const float* vft  = (const float*)d_in[1];
    const float* his  = (const float*)d_in[2];
    const float* cap  = (const float*)d_in[3];
    const float* qry  = (const float*)d_in[4];
    const int* trg_m  = (const int*)d_in[5];
    const int* his_m  = (const int*)d_in[6];
    const int* cap_m  = (const int*)d_in[7];
    const int* qry_m  = (const int*)d_in[8];
    const int* tmp_m  = (const int*)d_in[9];
    const float* attw = (const float*)d_in[10];
    const float* attb = (const float*)d_in[11];
    const float* ffw1 = (const float*)d_in[12];
    const float* ffb1 = (const float*)d_in[13];
    const float* ffw2 = (const float*)d_in[14];
    const float* ffb2 = (const float*)d_in[15];
    const float* lng  = (const float*)d_in[16];
    const float* lnb  = (const float*)d_in[17];
    float* out = (float*)d_out;

    float* cur   = sym_f(g_cur);
    float* lnA   = sym_f(g_lnA);
    float* lnB   = sym_f(g_lnB);
    float* lnC   = sym_f(g_lnC);
    float* qA    = sym_f(g_qA);
    float* qB    = sym_f(g_qB);
    float* ks    = sym_f(g_ks);
    float* vs    = sym_f(g_vs);
    float* abA   = sym_f(g_abA);
    float* abB   = sym_f(g_abB);
    float* ts    = sym_f(g_ts);
    float* st    = sym_f(g_st);
    float* ffhA  = sym_f(g_ffhA);
    float* ffhB  = sym_f(g_ffhB);
    float* big0  = sym_f(g_big0);
    float* big1  = sym_f(g_big1);
    float* big2  = sym_f(g_big2);
    float* big3  = sym_f(g_big3);
    float* big4  = sym_f(g_big4);
    float* big5  = sym_f(g_big5);
    float* big6  = sym_f(g_big6);
    float* big7  = sym_f(g_big7);
    int* map_perm = sym_i(g_map_perm);
    int* map_pt   = sym_i(g_map_pt);
    int* map_ps   = sym_i(g_map_ps);

    const long OFF_BWK = 0;
    const long OFF_BWV = 2*1024*1024;
    const long OFF_QT  = 4*1024*1024;
    const long OFF_SB  = 8*1024*1024;
    const long OFF_U2  = 12*1024*1024;
    const long OFF_PK  = 13*1024*1024;
    const long OFF_PV  = OFF_PK + 512*512;
    const long OFF_BV  = OFF_PV + 512*512;
    const long OFF_KV  = 26L*1024*1024;

    static cudaStream_t sA = nullptr, sB = nullptr, sC = nullptr;
    static cudaEvent_t eStart, eMaps, eVft, eCur, eC, eB, eEnd, eQKV0, eKV123;
    if (!sA) {
        cudaStreamCreateWithFlags(&sA, cudaStreamNonBlocking);
        cudaStreamCreateWithFlags(&sB, cudaStreamNonBlocking);
        cudaStreamCreateWithFlags(&sC, cudaStreamNonBlocking);
        cudaEventCreateWithFlags(&eStart, cudaEventDisableTiming);
        cudaEventCreateWithFlags(&eMaps,  cudaEventDisableTiming);
        cudaEventCreateWithFlags(&eVft,   cudaEventDisableTiming);
        cudaEventCreateWithFlags(&eCur,   cudaEventDisableTiming);
        cudaEventCreateWithFlags(&eC,     cudaEventDisableTiming);
        cudaEventCreateWithFlags(&eB,     cudaEventDisableTiming);
        cudaEventCreateWithFlags(&eEnd,   cudaEventDisableTiming);
        cudaEventCreateWithFlags(&eQKV0,  cudaEventDisableTiming);
        cudaEventCreateWithFlags(&eKV123, cudaEventDisableTiming);
    }

    cudaFuncSetAttribute((const void*)attn_tc_kernel,
                         cudaFuncAttributeMaxDynamicSharedMemorySize, 120*1024);

    #define AW(i,j) (attw + ((i)*4+(j))*DD*DD)
    #define ABI(i,j) (attb + ((i)*4+(j))*DD)

    auto launch_gemm = [](cudaStream_t st_, const float* A, const int* amap, int nch,
                          GemmChunks& ch, const float* R, const int* rmap,
                          int M, int N, int K, int relu) {
        if (M <= 2048 && N <= 2048) {
            dim3 grid(nch * (N/64), M/64);
            sgemm64_tc_kernel<<<grid, 128, 0, st_>>>(A, amap, ch, R, rmap, M, N, K, relu);
        } else {
            dim3 grid(nch * (N/128), M/128);
            sgemm_tc_kernel<<<grid, 256, 0, st_>>>(A, amap, ch, R, rmap, M, N, K, relu);
        }
    };
    auto gemmN = [&](cudaStream_t st_, const float* A, const int* amap, int nch,
                     const float* w0, const float* b0, float* c0,
                     const float* w1, const float* b1, float* c1,
                     const float* R, const int* rmap,
                     int M, int N, int K, int relu) {
        GemmChunks ch;
        ch.w[0] = w0; ch.b[0] = b0; ch.c[0] = c0;
        ch.w[1] = w1; ch.b[1] = b1; ch.c[1] = c1;
        ch.w[2] = nullptr; ch.b[2] = nullptr; ch.c[2] = nullptr;
        launch_gemm(st_, A, amap, nch, ch, R, rmap, M, N, K, relu);
    };
    auto gemm3 = [&](cudaStream_t st_, const float* A,
                     const float* w0, const float* b0, float* c0,
                     const float* w1, const float* b1, float* c1,
                     const float* w2, const float* b2, float* c2,
                     int M, int N, int K) {
        GemmChunks ch;
        ch.w[0] = w0; ch.b[0] = b0; ch.c[0] = c0;
        ch.w[1] = w1; ch.b[1] = b1; ch.c[1] = c1;
        ch.w[2] = w2; ch.b[2] = b2; ch.c[2] = c2;
        launch_gemm(st_, A, nullptr, 3, ch, nullptr, nullptr, M, N, K, 0);
    };
    auto gemm = [&](cudaStream_t st_, const float* A, const int* amap,
                    const float* W, const float* bias,
                    const float* R, const int* rmap, float* C,
                    int M, int N, int K, int relu) {
        gemmN(st_, A, amap, 1, W, bias, C, nullptr, nullptr, nullptr, R, rmap, M, N, K, relu);
    };
    auto attn = [](cudaStream_t st_, const float* Q, const float* K, const float* V, float* O,
                   int NB, int Lk, int qg, const int* mask, int mode, int mdiv) {
        int LkPad = (Lk + 31) & ~31;
        size_t sh = (size_t)(64*68 + LkPad*68 + 64*(LkPad+4)) * sizeof(float);
        attn_tc_kernel<<<dim3(NB, HH), 256, sh, st_>>>(Q, K, V, O, Lk, LkPad, qg, mask, mode, mdiv);
    };
    auto ln = [&](cudaStream_t st_, const float* in, int li, float* o, int rows) {
        ln_kernel<<<rows, 128, 0, st_>>>(in, lng + li*DD, lnb + li*DD, o);
    };

    // ---- fork ----
    cudaEventRecord(eStart, 0);
    cudaStreamWaitEvent(sA, eStart, 0);
    cudaStreamWaitEvent(sB, eStart, 0);
    cudaStreamWaitEvent(sC, eStart, 0);

    // sC phase 1: mha0 LN+QKV
    ln(sC, x, 0, lnC, NTOK_X);
    gemm3(sC, lnC, AW(0,0), ABI(0,0), qA, AW(0,1), ABI(0,1), ks, AW(0,2), ABI(0,2), vs,
          NTOK_X, DD, DD);
    cudaEventRecord(eQKV0, sC);
    // sC phase 2: mha1-3 K/V pairs
    {
        const float* kvsrc[3] = { his, cap, qry };
        const int    kvrows[3] = { BB*128, BB*64, BB*32 };
        for (int a = 0; a < 3; a++) {
            gemmN(sC, kvsrc[a], nullptr, 2,
                  AW(a+1,1), ABI(a+1,1), big2 + OFF_KV + (2*a)*1024*1024,
                  AW(a+1,2), ABI(a+1,2), big2 + OFF_KV + (2*a+1)*1024*1024,
                  nullptr, nullptr, kvrows[a], DD, DD, 0);
        }
        cudaEventRecord(eKV123, sC);
    }
    // sC phase 3: factored mha5/mha7 weight prep
    {
        gemmN(sC, AW(4,3), nullptr, 2, AW(5,1), nullptr, big3 + OFF_PK,
              AW(5,2), nullptr, big3 + OFF_PV, nullptr, nullptr, DD, DD, DD, 0);
        gemmN(sC, AW(6,3), nullptr, 2, AW(7,1), nullptr, big7 + OFF_PK,
              AW(7,2), nullptr, big7 + OFF_PV, nullptr, nullptr, DD, DD, DD, 0);
        bias_compose_kernel<<<64, 256, 0, sC>>>(ABI(4,3), AW(5,2), ABI(5,2), big3 + OFF_BV);
        bias_compose_kernel<<<64, 256, 0, sC>>>(ABI(6,3), AW(7,2), ABI(7,2), big7 + OFF_BV);
        build_bwk_kernel<<<(512*4096+255)/256, 256, 0, sC>>>(big3 + OFF_PK, big3 + OFF_BWK);
        build_bwv_kernel<<<(4096*512+255)/256, 256, 0, sC>>>(big3 + OFF_PV, big3 + OFF_BWV);
        build_bwk_kernel<<<(512*4096+255)/256, 256, 0, sC>>>(big7 + OFF_PK, big7 + OFF_BWK);
        build_bwv_kernel<<<(4096*512+255)/256, 256, 0, sC>>>(big7 + OFF_PV, big7 + OFF_BWV);
        cudaEventRecord(eC, sC);
    }

    // sA: maps
    build_maps_kernel<<<dim3(256, 3), 256, 0, sA>>>();
    cudaEventRecord(eMaps, sA);

    // sB: big vft projections
    cudaStreamWaitEvent(sB, eMaps, 0);
    gemmN(sB, vft, map_perm, 2, AW(4,1), ABI(4,1), big0, AW(4,2), ABI(4,2), big1,
          nullptr, nullptr, NTOK_VFT, DD, DD, 0);
    gemmN(sB, vft, nullptr, 2, AW(6,1), ABI(6,1), big4, AW(6,2), ABI(6,2), big5,
          nullptr, nullptr, NTOK_VFT, DD, DD, 0);
    cudaEventRecord(eVft, sB);

    // sA: mha0
    cudaStreamWaitEvent(sA, eQKV0, 0);
    attn(sA, qA, ks, vs, abA, BB, TTRG, 1, trg_m, 1, 1);
    gemm(sA, abA, nullptr, AW(0,3), ABI(0,3), x, nullptr, cur, NTOK_X, DD, DD, 0);

    // sA: mha1..3
    cudaStreamWaitEvent(sA, eKV123, 0);
    {
        const int  Lks[3]   = { 128, 64, 32 };
        const int* masks[3] = { his_m, cap_m, qry_m };
        for (int a = 0; a < 3; a++) {
            int wi = a + 1;
            ln(sA, cur, wi, lnA, NTOK_X);
            gemm(sA, lnA, nullptr, AW(wi,0), ABI(wi,0), nullptr, nullptr, qA, NTOK_X, DD, DD, 0);
            attn(sA, qA, big2 + OFF_KV + (2*a)*1024*1024, big2 + OFF_KV + (2*a+1)*1024*1024,
                 abA, BB, Lks[a], 1, masks[a], 2, 1);
            gemm(sA, abA, nullptr, AW(wi,3), ABI(wi,3), cur, nullptr, cur, NTOK_X, DD, DD, 0);
        }
    }
    cudaEventRecord(eCur, sA);

    // ========== chain A (sA) ==========
    ln(sA, cur, 4, lnA, NTOK_X);
    gemm(sA, lnA, nullptr, AW(4,0), ABI(4,0), nullptr, nullptr, qA, NTOK_X, DD, DD, 0);
    cudaStreamWaitEvent(sA, eVft, 0);
    attn(sA, qA, big0, big1, big2, BB*SS, TT, SS, tmp_m, 2, SS);
    ln(sA, cur, 5, lnA, NTOK_X);
    gemm(sA, lnA, nullptr, AW(5,0), ABI(5,0), nullptr, nullptr, qA, NTOK_X, DD, DD, 0);
    cudaStreamWaitEvent(sA, eC, 0);
    gemm(sA, cur, nullptr, AW(5,2), big3 + OFF_BV, nullptr, nullptr, big3 + OFF_U2,
         NTOK_X, DD, DD, 0);
    gemm(sA, qA, nullptr, big3 + OFF_BWK, nullptr, nullptr, nullptr, big3 + OFF_QT,
         NTOK_X, 4096, DD, 0);
    attn_wide_kernel<<<NTOK_X, 256, 0, sA>>>(big3 + OFF_QT, big2, map_pt, big3 + OFF_SB,
                                             SS, nullptr, 0, 1);
    gemm(sA, big3 + OFF_SB, nullptr, big3 + OFF_BWV, nullptr, big3 + OFF_U2, nullptr,
         abA, NTOK_X, DD, 4096, 0);
    gemm(sA, abA, nullptr, AW(5,3), ABI(5,3), cur, nullptr, ts, NTOK_X, DD, DD, 0);
    ln(sA, ts, 6, lnA, NTOK_X);
    gemm(sA, lnA, nullptr, ffw1 + 0*DD*DFF, ffb1 + 0*DFF, nullptr, nullptr, ffhA, NTOK_X, DFF, DD, 1);
    gemm(sA, ffhA, nullptr, ffw2 + 0*DFF*DD, ffb2 + 0*DD, ts, nullptr, ts, NTOK_X, DD, DFF, 0);

    // ========== chain B (sB) ==========
    cudaStreamWaitEvent(sB, eCur, 0);
    ln(sB, cur, 7, lnB, NTOK_X);
    gemm(sB, lnB, nullptr, AW(6,0), ABI(6,0), nullptr, nullptr, qB, NTOK_X, DD, DD, 0);
    attn(sB, qB, big4, big5, big6, BB*TT, SS, TT, nullptr, 0, 1);
    ln(sB, cur, 8, lnB, NTOK_X);
    gemm(sB, lnB, nullptr, AW(7,0), ABI(7,0), nullptr, nullptr, qB, NTOK_X, DD, DD, 0);
    cudaStreamWaitEvent(sB, eC, 0);
    gemm(sB, cur, nullptr, AW(7,2), big7 + OFF_BV, nullptr, nullptr, big7 + OFF_U2,
         NTOK_X, DD, DD, 0);
    gemm(sB, qB, nullptr, big7 + OFF_BWK, nullptr, nullptr, nullptr, big7 + OFF_QT,
         NTOK_X, 4096, DD, 0);
    attn_wide_kernel<<<NTOK_X, 256, 0, sB>>>(big7 + OFF_QT, big6, map_ps, big7 + OFF_SB,
                                             TT, tmp_m, 2, TTRG);
    gemm(sB, big7 + OFF_SB, nullptr, big7 + OFF_BWV, nullptr, big7 + OFF_U2, nullptr,
         abB, NTOK_X, DD, 4096, 0);
    gemm(sB, abB, nullptr, AW(7,3), ABI(7,3), cur, nullptr, st, NTOK_X, DD, DD, 0);
    ln(sB, st, 9, lnB, NTOK_X);
    gemm(sB, lnB, nullptr, ffw1 + 1*DD*DFF, ffb1 + 1*DFF, nullptr, nullptr, ffhB, NTOK_X, DFF, DD, 1);
    gemm(sB, ffhB, nullptr, ffw2 + 1*DFF*DD, ffb2 + 1*DD, st, nullptr, st, NTOK_X, DD, DFF, 0);
    cudaEventRecord(eB, sB);

    // ---- join on sA ----
    cudaStreamWaitEvent(sA, eB, 0);
    add_kernel<<<(NTOK_X*DD + 255)/256, 256, 0, sA>>>(ts, st, cur, NTOK_X*DD);
    ln(sA, cur, 10, lnA, NTOK_X);
    gemm(sA, lnA, nullptr, ffw1 + 2*DD*DFF, ffb1 + 2*DFF, nullptr, nullptr, ffhA, NTOK_X, DFF, DD, 1);
    gemm(sA, ffhA, nullptr, ffw2 + 2*DFF*DD, ffb2 + 2*DD, cur, nullptr, out, NTOK_X, DD, DFF, 0);

    cudaEventRecord(eEnd, sA);
    cudaStreamWaitEvent(0, eEnd, 0);

    #undef AW
    #undef ABI
}

// round 15
// speedup vs baseline: 1.3925x; 1.3925x over previous
#include <cuda_runtime.h>
#include <math.h>
#include <stdint.h>

// ---------------- problem constants ----------------
#define BB   16
#define TTRG 64
#define TT   64
#define SS   49
#define DD   512
#define DFF  2048
#define HH   8
#define NTOK_X    (BB*TTRG)          // 1024
#define NTOK_VFT  (BB*TT*SS)         // 50176
#define NTOK_SOUT (BB*TT*TTRG)       // 65536

// ---------------- scratch ----------------
__device__ float g_cur [NTOK_X*DD];
__device__ float g_lnA [NTOK_X*DD];
__device__ float g_lnB [NTOK_X*DD];
__device__ float g_lnC [NTOK_X*DD];
__device__ float g_qA  [NTOK_X*DD];
__device__ float g_qB  [NTOK_X*DD];
__device__ float g_ks  [2048*DD];
__device__ float g_vs  [2048*DD];
__device__ float g_abA [NTOK_X*DD];
__device__ float g_abB [NTOK_X*DD];
__device__ float g_ts  [NTOK_X*DD];
__device__ float g_st  [NTOK_X*DD];
__device__ float g_ffhA[NTOK_X*DFF];
__device__ float g_ffhB[NTOK_X*DFF];
__device__ float g_big0[NTOK_SOUT*DD];
__device__ float g_big1[NTOK_SOUT*DD];
__device__ float g_big2[NTOK_SOUT*DD];   // head: ao_A; tail @26M: mha1-3 KV
__device__ float g_big3[NTOK_SOUT*DD];   // chain A scratch
__device__ float g_big4[NTOK_SOUT*DD];
__device__ float g_big5[NTOK_SOUT*DD];
__device__ float g_big6[NTOK_SOUT*DD];
__device__ float g_big7[NTOK_SOUT*DD];   // chain B scratch
__device__ int   g_map_perm[NTOK_VFT];
__device__ int   g_map_pt  [NTOK_VFT];
__device__ int   g_map_ps  [NTOK_SOUT];

// ---------------- fused map builder ----------------
__device__ __forceinline__ int swap_map(int m, int Bd, int Cd) {
    int c = m % Cd;
    int b = (m / Cd) % Bd;
    int a = m / (Cd*Bd);
    return (a*Cd + c)*Bd + b;
}
__global__ void build_maps_kernel() {
    int m = blockIdx.x*256 + threadIdx.x;
    int job = blockIdx.y;
    if (job == 0)      { if (m < NTOK_VFT)  g_map_perm[m] = swap_map(m, SS, TT); }
    else if (job == 1) { if (m < NTOK_VFT)  g_map_pt[m]   = swap_map(m, TTRG, SS); }
    else               { if (m < NTOK_SOUT) g_map_ps[m]   = swap_map(m, TTRG, TT); }
}

// ---------------- block-diagonal weight builders ----------------
__global__ void build_bwk_kernel(const float* __restrict__ W, float* __restrict__ BWK) {
    int idx = blockIdx.x*256 + threadIdx.x;
    if (idx >= 512*4096) return;
    int k = idx >> 12, n = idx & 4095;
    int hk = k >> 6, c = k & 63;
    int hn = n >> 9, d = n & 511;
    BWK[idx] = (hk == hn) ? W[d*512 + hk*64 + c] : 0.0f;
}
__global__ void build_bwv_kernel(const float* __restrict__ W, float* __restrict__ BWV) {
    int idx = blockIdx.x*256 + threadIdx.x;
    if (idx >= 4096*512) return;
    int k = idx >> 9, n = idx & 511;
    int hk = k >> 9, d = k & 511;
    int hn = n >> 6, e = n & 63;
    BWV[idx] = (hk == hn) ? W[d*512 + hn*64 + e] : 0.0f;
}
__global__ void bias_compose_kernel(const float* __restrict__ b1, const float* __restrict__ W,
                                    const float* __restrict__ b2, float* __restrict__ biasv) {
    int n = blockIdx.x*8 + (threadIdx.x >> 5);
    int lane = threadIdx.x & 31;
    if (n >= 512) return;
    float s = 0.0f;
    for (int d = lane; d < 512; d += 32) s += b1[d] * W[d*512 + n];
    #pragma unroll
    for (int o = 16; o; o >>= 1) s += __shfl_xor_sync(0xffffffffu, s, o);
    if (lane == 0) biasv[n] = s + b2[n];
}

// ---------------- layernorm (D=512); optional second input added first ----------------
__global__ __launch_bounds__(128) void ln_kernel(const float* __restrict__ in,
                                                 const float* __restrict__ in2,  // may be null
                                                 float* __restrict__ sum_out,    // may be null
                                                 const float* __restrict__ gamma,
                                                 const float* __restrict__ beta,
                                                 float* __restrict__ out) {
    int row = blockIdx.x;
    int tid = threadIdx.x;
    float4 v = reinterpret_cast<const float4*>(in + (long)row*DD)[tid];
    if (in2) {
        float4 w = reinterpret_cast<const float4*>(in2 + (long)row*DD)[tid];
        v.x += w.x; v.y += w.y; v.z += w.z; v.w += w.w;
        if (sum_out) reinterpret_cast<float4*>(sum_out + (long)row*DD)[tid] = v;
    }
    float s = v.x + v.y + v.z + v.w;
    float q = v.x*v.x + v.y*v.y + v.z*v.z + v.w*v.w;
    #pragma unroll
    for (int o = 16; o; o >>= 1) {
        s += __shfl_xor_sync(0xffffffffu, s, o);
        q += __shfl_xor_sync(0xffffffffu, q, o);
    }
    __shared__ float ssum[4], ssq[4];
    int warp = tid >> 5, lane = tid & 31;
    if (lane == 0) { ssum[warp] = s; ssq[warp] = q; }
    __syncthreads();
    __shared__ float smean, sinv;
    if (tid == 0) {
        float S = ssum[0]+ssum[1]+ssum[2]+ssum[3];
        float Q = ssq[0]+ssq[1]+ssq[2]+ssq[3];
        float mean = S * (1.0f/DD);
        float var  = Q * (1.0f/DD) - mean*mean;
        float sd   = sqrtf(fmaxf(var, 0.0f));
        smean = mean;
        sinv  = 1.0f / (sd + 1e-6f);
    }
    __syncthreads();
    float mean = smean, inv = sinv;
    float4 gv = reinterpret_cast<const float4*>(gamma)[tid];
    float4 bv = reinterpret_cast<const float4*>(beta)[tid];
    float4 o;
    o.x = gv.x*(v.x-mean)*inv + bv.x;
    o.y = gv.y*(v.y-mean)*inv + bv.y;
    o.z = gv.z*(v.z-mean)*inv + bv.z;
    o.w = gv.w*(v.w-mean)*inv + bv.w;
    reinterpret_cast<float4*>(out + (long)row*DD)[tid] = o;
}

// ---------------- tf32/cp.async/ldmatrix helpers ----------------
__device__ __forceinline__ void mma_tf32(float* c, const uint32_t* a, const uint32_t* b) {
    asm volatile("mma.sync.aligned.m16n8k8.row.col.f32.tf32.tf32.f32 "
        "{%0,%1,%2,%3}, {%4,%5,%6,%7}, {%8,%9}, {%0,%1,%2,%3};"
        : "+f"(c[0]), "+f"(c[1]), "+f"(c[2]), "+f"(c[3])
        : "r"(a[0]), "r"(a[1]), "r"(a[2]), "r"(a[3]), "r"(b[0]), "r"(b[1]));
}
__device__ __forceinline__ void cp_async16(void* smem_ptr, const void* gptr) {
    uint32_t s = (uint32_t)__cvta_generic_to_shared(smem_ptr);
    asm volatile("cp.async.cg.shared.global [%0], [%1], 16;" :: "r"(s), "l"(gptr));
}
#define CP_COMMIT() asm volatile("cp.async.commit_group;")
#define CP_WAIT0()  asm volatile("cp.async.wait_group 0;")
__device__ __forceinline__ void ldsm_x4(uint32_t* r, const void* p) {
    uint32_t a = (uint32_t)__cvta_generic_to_shared(p);
    asm volatile("ldmatrix.sync.aligned.m8n8.x4.shared.b16 {%0,%1,%2,%3}, [%4];"
        : "=r"(r[0]), "=r"(r[1]), "=r"(r[2]), "=r"(r[3]) : "r"(a));
}

// ---------------- multi-chunk tf32 GEMM (128x128 tile, Kc=32) ----------------
#define TCP 136
#define ASP 36

struct GemmChunks {
    const float* w[3];
    const float* b[3];
    float*       c[3];
};

__global__ __launch_bounds__(256, 2) void sgemm_tc_kernel(
    const float* __restrict__ A, const int* __restrict__ amap,
    GemmChunks ch,
    const float* __restrict__ R, const int* __restrict__ rmap,
    int M, int N, int K, int relu)
{
    __shared__ float As[2][128][ASP];
    __shared__ float Bs[2][32][TCP];
    __shared__ int rowm[128];
    int tid = threadIdx.x;
    int ntiles = N >> 7;
    int widx = blockIdx.x / ntiles;
    int n0 = (blockIdx.x % ntiles) << 7;
    int m0 = blockIdx.y << 7;
    const float* W    = ch.w[widx];
    const float* bias = ch.b[widx];
    float*       C    = ch.c[widx];
    if (tid < 128) rowm[tid] = amap ? amap[m0 + tid] : (m0 + tid);
    __syncthreads();

    int wid = tid >> 5, lane = tid & 31;
    int warp_m = wid >> 2, warp_n = wid & 3;
    int gr = lane >> 2, gc = lane & 3;
    int lrow = lane & 15, lkq = (lane >> 4) << 2;

    int arow = tid >> 1, ak = (tid & 1) << 4;
    const float* aptr = A + (long)rowm[arow]*K + ak;
    int bk = tid >> 5, bn = (lane) << 2;
    const float* bptr = W + (long)bk*N + n0 + bn;

    float acc[4][4][4];
    #pragma unroll
    for (int i = 0; i < 4; i++)
        #pragma unroll
        for (int j = 0; j < 4; j++)
            #pragma unroll
            for (int u = 0; u < 4; u++) acc[i][j][u] = 0.0f;

    #pragma unroll
    for (int q = 0; q < 4; q++)
        cp_async16(&As[0][arow][ak + q*4], aptr + q*4);
    #pragma unroll
    for (int q = 0; q < 4; q++)
        cp_async16(&Bs[0][bk + q*8][bn], bptr + (long)(q*8)*N);
    CP_COMMIT();
    CP_WAIT0();
    __syncthreads();

    int mbase = warp_m << 6;
    int buf = 0;
    for (int k0 = 0; k0 < K; k0 += 32) {
        bool has_next = (k0 + 32) < K;
        if (has_next) {
            #pragma unroll
            for (int q = 0; q < 4; q++)
                cp_async16(&As[buf^1][arow][ak + q*4], aptr + k0 + 32 + q*4);
            #pragma unroll
            for (int q = 0; q < 4; q++)
                cp_async16(&Bs[buf^1][bk + q*8][bn], bptr + (long)(k0 + 32 + q*8)*N);
            CP_COMMIT();
        }
        uint32_t afb[2][4][4];
        #pragma unroll
        for (int mt = 0; mt < 4; mt++)
            ldsm_x4(afb[0][mt], &As[buf][mbase + (mt << 4) + lrow][lkq]);
        #pragma unroll
        for (int ks = 0; ks < 4; ks++) {
            int cur = ks & 1;
            if (ks < 3) {
                #pragma unroll
                for (int mt = 0; mt < 4; mt++)
                    ldsm_x4(afb[cur ^ 1][mt],
                            &As[buf][mbase + (mt << 4) + lrow][((ks + 1) << 3) + lkq]);
            }
            int kb = ks << 3;
            uint32_t bf[4][2];
            #pragma unroll
            for (int nt = 0; nt < 4; nt++) {
                int nb = (warp_n << 5) + (nt << 3) + gr;
                bf[nt][0] = __float_as_uint(Bs[buf][kb+gc  ][nb]);
                bf[nt][1] = __float_as_uint(Bs[buf][kb+gc+4][nb]);
            }
            #pragma unroll
            for (int mt = 0; mt < 4; mt++)
                #pragma unroll
                for (int nt = 0; nt < 4; nt++)
                    mma_tf32(acc[mt][nt], afb[cur][mt], bf[nt]);
        }
        if (has_next) CP_WAIT0();
        __syncthreads();
        buf ^= 1;
    }

    #pragma unroll
    for (int mt = 0; mt < 4; mt++) {
        #pragma unroll
        for (int half = 0; half < 2; half++) {
            int m = m0 + (warp_m << 6) + (mt << 4) + gr + (half << 3);
            long rbase = 0;
            if (R) rbase = (long)(rmap ? rmap[m] : m) * N;
            #pragma unroll
            for (int nt = 0; nt < 4; nt++) {
                int n = n0 + (warp_n << 5) + (nt << 3) + (gc << 1);
                float v0 = acc[mt][nt][half*2 + 0];
                float v1 = acc[mt][nt][half*2 + 1];
                if (bias) { v0 += bias[n]; v1 += bias[n+1]; }
                if (relu) { v0 = fmaxf(v0, 0.0f); v1 = fmaxf(v1, 0.0f); }
                if (R) {
                    float2 rv = *reinterpret_cast<const float2*>(R + rbase + n);
                    v0 += rv.x; v1 += rv.y;
                }
                *reinterpret_cast<float2*>(C + (long)m*N + n) = make_float2(v0, v1);
            }
        }
    }
}

// ---------------- tensor-core attention, Lq=64, dk=64 ----------------
__global__ __launch_bounds__(256) void attn_tc_kernel(
    const float* __restrict__ Q, const float* __restrict__ Kg,
    const float* __restrict__ Vg, float* __restrict__ O,
    int Lk, int LkPad, int q_group,
    const int* __restrict__ mask, int mask_mode, int mask_div)
{
    extern __shared__ float sm[];
    float* sQ  = sm;
    float* sKV = sm + 64*68;
    float* sS  = sKV + LkPad*68;
    int batch = blockIdx.x, h = blockIdx.y;
    int tid = threadIdx.x;
    int qbase = (batch / q_group) * 64;
    int sp = LkPad + 4;

    int wid = tid >> 5, lane = tid & 31;
    int warp_m = wid >> 2, warp_n = wid & 3;
    int gr = lane >> 2, gc = lane & 3;
    int nw  = LkPad >> 2;
    int ntn = LkPad >> 5;

    for (int c4 = tid; c4 < 64*16; c4 += 256) {
        int i = c4 >> 4, d = (c4 & 15) << 2;
        cp_async16(&sQ[i*68 + d], &Q[(long)(qbase + i)*DD + h*64 + d]);
    }
    for (int c4 = tid; c4 < Lk*16; c4 += 256) {
        int j = c4 >> 4, d = (c4 & 15) << 2;
        cp_async16(&sKV[j*68 + d], &Kg[(long)(batch*Lk + j)*DD + h*64 + d]);
    }
    CP_COMMIT();
    for (int idx = Lk*64 + tid; idx < LkPad*64; idx += 256) {
        int j = idx >> 6, d = idx & 63;
        sKV[j*68 + d] = 0.0f;
    }
    CP_WAIT0();
    __syncthreads();

    {
        float acc[2][4][4];
        #pragma unroll
        for (int mt = 0; mt < 2; mt++)
            #pragma unroll
            for (int nt = 0; nt < 4; nt++)
                #pragma unroll
                for (int u = 0; u < 4; u++) acc[mt][nt][u] = 0.0f;

        for (int kb = 0; kb < 64; kb += 8) {
            uint32_t af[2][4];
            #pragma unroll
            for (int mt = 0; mt < 2; mt++) {
                int mr = warp_m*32 + mt*16 + gr;
                af[mt][0] = __float_as_uint(sQ[mr*68 + kb+gc]);
                af[mt][1] = __float_as_uint(sQ[(mr+8)*68 + kb+gc]);
                af[mt][2] = __float_as_uint(sQ[mr*68 + kb+gc+4]);
                af[mt][3] = __float_as_uint(sQ[(mr+8)*68 + kb+gc+4]);
            }
            for (int nt = 0; nt < ntn; nt++) {
                int nc = warp_n*nw + nt*8 + gr;
                uint32_t bf[2];
                bf[0] = __float_as_uint(sKV[nc*68 + kb+gc]);
                bf[1] = __float_as_uint(sKV[nc*68 + kb+gc+4]);
                mma_tf32(acc[0][nt], af[0], bf);
                mma_tf32(acc[1][nt], af[1], bf);
            }
        }
        #pragma unroll
        for (int mt = 0; mt < 2; mt++)
            for (int nt = 0; nt < ntn; nt++) {
                int row = warp_m*32 + mt*16 + gr;
                int col = warp_n*nw + nt*8 + (gc << 1);
                sS[row*sp + col]       = acc[mt][nt][0]*0.125f;
                sS[row*sp + col + 1]   = acc[mt][nt][1]*0.125f;
                sS[(row+8)*sp + col]   = acc[mt][nt][2]*0.125f;
                sS[(row+8)*sp + col+1] = acc[mt][nt][3]*0.125f;
            }
    }
    __syncthreads();

    for (int c4 = tid; c4 < Lk*16; c4 += 256) {
        int j = c4 >> 4, d = (c4 & 15) << 2;
        cp_async16(&sKV[j*68 + d], &Vg[(long)(batch*Lk + j)*DD + h*64 + d]);
    }
    CP_COMMIT();

    for (int i = wid; i < 64; i += 8) {
        float mx = -3.4e38f;
        for (int j = lane; j < Lk; j += 32) {
            float v = sS[i*sp + j];
            bool dead = false;
            if (mask_mode == 1) dead = (mask[(long)(batch*64 + i)*Lk + j] == 0);
            else if (mask_mode == 2) dead = (mask[(batch/mask_div)*Lk + j] == 0);
            if (dead) { v = -1e9f; sS[i*sp + j] = v; }
            mx = fmaxf(mx, v);
        }
        #pragma unroll
        for (int o = 16; o; o >>= 1) mx = fmaxf(mx, __shfl_xor_sync(0xffffffffu, mx, o));
        float sum = 0.0f;
        for (int j = lane; j < Lk; j += 32) {
            float e = __expf(sS[i*sp + j] - mx);
            sS[i*sp + j] = e;
            sum += e;
        }
        #pragma unroll
        for (int o = 16; o; o >>= 1) sum += __shfl_xor_sync(0xffffffffu, sum, o);
        float inv = 1.0f / sum;
        for (int j = lane; j < Lk; j += 32) sS[i*sp + j] *= inv;
        for (int j = Lk + lane; j < LkPad; j += 32) sS[i*sp + j] = 0.0f;
    }
    CP_WAIT0();
    __syncthreads();

    {
        float acc[2][2][4];
        #pragma unroll
        for (int mt = 0; mt < 2; mt++)
            #pragma unroll
            for (int nt = 0; nt < 2; nt++)
                #pragma unroll
                for (int u = 0; u < 4; u++) acc[mt][nt][u] = 0.0f;

        for (int kb = 0; kb < LkPad; kb += 8) {
            uint32_t af[2][4];
            #pragma unroll
            for (int mt = 0; mt < 2; mt++) {
                int mr = warp_m*32 + mt*16 + gr;
                af[mt][0] = __float_as_uint(sS[mr*sp + kb+gc]);
                af[mt][1] = __float_as_uint(sS[(mr+8)*sp + kb+gc]);
                af[mt][2] = __float_as_uint(sS[mr*sp + kb+gc+4]);
                af[mt][3] = __float_as_uint(sS[(mr+8)*sp + kb+gc+4]);
            }
            #pragma unroll
            for (int nt = 0; nt < 2; nt++) {
                int nc = warp_n*16 + nt*8 + gr;
                uint32_t bf[2];
                int k0r = kb+gc, k1r = kb+gc+4;
                bf[0] = (k0r < Lk) ? __float_as_uint(sKV[k0r*68 + nc]) : 0u;
                bf[1] = (k1r < Lk) ? __float_as_uint(sKV[k1r*68 + nc]) : 0u;
                mma_tf32(acc[0][nt], af[0], bf);
                mma_tf32(acc[1][nt], af[1], bf);
            }
        }
        #pragma unroll
        for (int mt = 0; mt < 2; mt++)
            #pragma unroll
            for (int nt = 0; nt < 2; nt++) {
                int i = warp_m*32 + mt*16 + gr;
                int d = warp_n*16 + nt*8 + (gc << 1);
                long base = (long)(batch*64 + i)*DD + h*64 + d;
                *reinterpret_cast<float2*>(O + base) =
                    make_float2(acc[mt][nt][0], acc[mt][nt][1]);
                *reinterpret_cast<float2*>(O + base + 8*DD) =
                    make_float2(acc[mt][nt][2], acc[mt][nt][3]);
            }
    }
}

// ---------------- wide Lq=1 attention over RAW rows ----------------
__global__ __launch_bounds__(256) void attn_wide_kernel(
    const float* __restrict__ QT, const float* __restrict__ SRC,
    const int* __restrict__ map, float* __restrict__ SB,
    int Lk, const int* __restrict__ mask, int mask_mode, int mask_div)
{
    __shared__ float qt8[8*512];
    __shared__ float krow[8][516];
    __shared__ float sS[8][72];
    __shared__ int   rows[64];
    int q = blockIdx.x;
    int tid = threadIdx.x;
    int h = tid >> 5, lane = tid & 31;

    for (int i = tid; i < 4096; i += 256) qt8[i] = QT[(long)q*4096 + i];
    if (tid < Lk) rows[tid] = map[q*Lk + tid];
    __syncthreads();

    for (int jt = 0; jt < Lk; jt += 8) {
        int nj = min(8, Lk - jt);
        for (int idx = tid; idx < nj*512; idx += 256) {
            int j = idx >> 9, d = idx & 511;
            krow[j][d] = SRC[(long)rows[jt + j]*512 + d];
        }
        __syncthreads();
        for (int j = 0; j < nj; j++) {
            float s = 0.0f;
            #pragma unroll
            for (int i = 0; i < 16; i++)
                s += qt8[h*512 + i*32 + lane] * krow[j][i*32 + lane];
            #pragma unroll
            for (int o = 16; o; o >>= 1) s += __shfl_xor_sync(0xffffffffu, s, o);
            if (lane == 0) sS[h][jt + j] = s * 0.125f;
        }
        __syncthreads();
    }

    {
        float mx = -3.4e38f;
        for (int j = lane; j < Lk; j += 32) {
            float v = sS[h][j];
            if (mask_mode == 2 && mask[(q/mask_div)*Lk + j] == 0) { v = -1e9f; sS[h][j] = v; }
            mx = fmaxf(mx, v);
        }
        #pragma unroll
        for (int o = 16; o; o >>= 1) mx = fmaxf(mx, __shfl_xor_sync(0xffffffffu, mx, o));
        float sum = 0.0f;
        for (int j = lane; j < Lk; j += 32) {
            float e = __expf(sS[h][j] - mx);
            sS[h][j] = e;
            sum += e;
        }
        #pragma unroll
        for (int o = 16; o; o >>= 1) sum += __shfl_xor_sync(0xffffffffu, sum, o);
        float inv = 1.0f / sum;
        for (int j = lane; j < Lk; j += 32) sS[h][j] *= inv;
    }
    __syncthreads();

    float acc[16];
    #pragma unroll
    for (int i = 0; i < 16; i++) acc[i] = 0.0f;
    for (int jt = 0; jt < Lk; jt += 8) {
        int nj = min(8, Lk - jt);
        for (int idx = tid; idx < nj*512; idx += 256) {
            int j = idx >> 9, d = idx & 511;
            krow[j][d] = SRC[(long)rows[jt + j]*512 + d];
        }
        __syncthreads();
        for (int j = 0; j < nj; j++) {
            float p = sS[h][jt + j];
            #pragma unroll
            for (int i = 0; i < 16; i++)
                acc[i] += p * krow[j][i*32 + lane];
        }
        __syncthreads();
    }
    #pragma unroll
    for (int i = 0; i < 16; i++)
        SB[(long)q*4096 + h*512 + i*32 + lane] = acc[i];
}

// ---------------- host ----------------
static float* sym_f(const void* s) { void* p = nullptr; cudaGetSymbolAddress(&p, s); return (float*)p; }
static int*   sym_i(const void* s) { void* p = nullptr; cudaGetSymbolAddress(&p, s); return (int*)p; }

extern "C" void kernel_launch(void* const* d_in, const int* in_sizes, int n_in,
                              void* d_out, int out_size) {
    const float* x    = (const float*)d_in[0];
    const float* vft  = (const float*)d_in[1];
    const float* his  = (const float*)d_in[2];
    const float* cap  = (const float*)d_in[3];
    const float* qry  = (const float*)d_in[4];
    const int* trg_m  = (const int*)d_in[5];
    const int* his_m  = (const int*)d_in[6];
    const int* cap_m  = (const int*)d_in[7];
    const int* qry_m  = (const int*)d_in[8];
    const int* tmp_m  = (const int*)d_in[9];
    const float* attw = (const float*)d_in[10];
    const float* attb = (const float*)d_in[11];
    const float* ffw1 = (const float*)d_in[12];
    const float* ffb1 = (const float*)d_in[13];
    const float* ffw2 = (const float*)d_in[14];
    const float* ffb2 = (const float*)d_in[15];
    const float* lng  = (const float*)d_in[16];
    const float* lnb  = (const float*)d_in[17];
    float* out = (float*)d_out;

    float* cur   = sym_f(g_cur);
    float* lnA   = sym_f(g_lnA);
    float* lnB   = sym_f(g_lnB);
    float* lnC   = sym_f(g_lnC);
    float* qA    = sym_f(g_qA);
    float* qB    = sym_f(g_qB);
    float* ks    = sym_f(g_ks);
    float* vs    = sym_f(g_vs);
    float* abA   = sym_f(g_abA);
    float* abB   = sym_f(g_abB);
    float* ts    = sym_f(g_ts);
    float* st    = sym_f(g_st);
    float* ffhA  = sym_f(g_ffhA);
    float* ffhB  = sym_f(g_ffhB);
    float* big0  = sym_f(g_big0);
    float* big1  = sym_f(g_big1);
    float* big2  = sym_f(g_big2);
    float* big3  = sym_f(g_big3);
    float* big4  = sym_f(g_big4);
    float* big5  = sym_f(g_big5);
    float* big6  = sym_f(g_big6);
    float* big7  = sym_f(g_big7);
    int* map_perm = sym_i(g_map_perm);
    int* map_pt   = sym_i(g_map_pt);
    int* map_ps   = sym_i(g_map_ps);

    const long OFF_BWK = 0;
    const long OFF_BWV = 2*1024*1024;
    const long OFF_QT  = 4*1024*1024;
    const long OFF_SB  = 8*1024*1024;
    const long OFF_U2  = 12*1024*1024;
    const long OFF_PK  = 13*1024*1024;
    const long OFF_PV  = OFF_PK + 512*512;
    const long OFF_BV  = OFF_PV + 512*512;
    const long OFF_KV  = 26L*1024*1024;

    static cudaStream_t sA = nullptr, sB = nullptr, sC = nullptr;
    static cudaEvent_t eStart, eMaps, eVft, eCur, eC, eB, eEnd, eQKV0, eKV123;
    if (!sA) {
        cudaStreamCreateWithFlags(&sA, cudaStreamNonBlocking);
        cudaStreamCreateWithFlags(&sB, cudaStreamNonBlocking);
        cudaStreamCreateWithFlags(&sC, cudaStreamNonBlocking);
        cudaEventCreateWithFlags(&eStart, cudaEventDisableTiming);
        cudaEventCreateWithFlags(&eMaps,  cudaEventDisableTiming);
        cudaEventCreateWithFlags(&eVft,   cudaEventDisableTiming);
        cudaEventCreateWithFlags(&eCur,   cudaEventDisableTiming);
        cudaEventCreateWithFlags(&eC,     cudaEventDisableTiming);
        cudaEventCreateWithFlags(&eB,     cudaEventDisableTiming);
        cudaEventCreateWithFlags(&eEnd,   cudaEventDisableTiming);
        cudaEventCreateWithFlags(&eQKV0,  cudaEventDisableTiming);
        cudaEventCreateWithFlags(&eKV123, cudaEventDisableTiming);
    }

    cudaFuncSetAttribute((const void*)attn_tc_kernel,
                         cudaFuncAttributeMaxDynamicSharedMemorySize, 120*1024);

    #define AW(i,j) (attw + ((i)*4+(j))*DD*DD)
    #define ABI(i,j) (attb + ((i)*4+(j))*DD)

    auto gemmN = [](cudaStream_t st_, const float* A, const int* amap, int nch,
                    const float* w0, const float* b0, float* c0,
                    const float* w1, const float* b1, float* c1,
                    const float* R, const int* rmap,
                    int M, int N, int K, int relu) {
        GemmChunks ch;
        ch.w[0] = w0; ch.b[0] = b0; ch.c[0] = c0;
        ch.w[1] = w1; ch.b[1] = b1; ch.c[1] = c1;
        ch.w[2] = nullptr; ch.b[2] = nullptr; ch.c[2] = nullptr;
        dim3 grid(nch * (N/128), M/128);
        sgemm_tc_kernel<<<grid, 256, 0, st_>>>(A, amap, ch, R, rmap, M, N, K, relu);
    };
    auto gemm3 = [](cudaStream_t st_, const float* A,
                    const float* w0, const float* b0, float* c0,
                    const float* w1, const float* b1, float* c1,
                    const float* w2, const float* b2, float* c2,
                    int M, int N, int K) {
        GemmChunks ch;
        ch.w[0] = w0; ch.b[0] = b0; ch.c[0] = c0;
        ch.w[1] = w1; ch.b[1] = b1; ch.c[1] = c1;
        ch.w[2] = w2; ch.b[2] = b2; ch.c[2] = c2;
        dim3 grid(3 * (N/128), M/128);
        sgemm_tc_kernel<<<grid, 256, 0, st_>>>(A, nullptr, ch, nullptr, nullptr, M, N, K, 0);
    };
    auto gemm = [&](cudaStream_t st_, const float* A, const int* amap,
                    const float* W, const float* bias,
                    const float* R, const int* rmap, float* C,
                    int M, int N, int K, int relu) {
        gemmN(st_, A, amap, 1, W, bias, C, nullptr, nullptr, nullptr, R, rmap, M, N, K, relu);
    };
    auto attn = [](cudaStream_t st_, const float* Q, const float* K, const float* V, float* O,
                   int NB, int Lk, int qg, const int* mask, int mode, int mdiv) {
        int LkPad = (Lk + 31) & ~31;
        size_t sh = (size_t)(64*68 + LkPad*68 + 64*(LkPad+4)) * sizeof(float);
        attn_tc_kernel<<<dim3(NB, HH), 256, sh, st_>>>(Q, K, V, O, Lk, LkPad, qg, mask, mode, mdiv);
    };
    auto ln = [&](cudaStream_t st_, const float* in, int li, float* o, int rows) {
        ln_kernel<<<rows, 128, 0, st_>>>(in, nullptr, nullptr, lng + li*DD, lnb + li*DD, o);
    };
    auto add_ln = [&](cudaStream_t st_, const float* a, const float* b, float* sum,
                      int li, float* o, int rows) {
        ln_kernel<<<rows, 128, 0, st_>>>(a, b, sum, lng + li*DD, lnb + li*DD, o);
    };

    // ---- fork ----
    cudaEventRecord(eStart, 0);
    cudaStreamWaitEvent(sA, eStart, 0);
    cudaStreamWaitEvent(sB, eStart, 0);
    cudaStreamWaitEvent(sC, eStart, 0);

    // sC phase 1: mha0 LN+QKV
    ln(sC, x, 0, lnC, NTOK_X);
    gemm3(sC, lnC, AW(0,0), ABI(0,0), qA, AW(0,1), ABI(0,1), ks, AW(0,2), ABI(0,2), vs,
          NTOK_X, DD, DD);
    cudaEventRecord(eQKV0, sC);
    // sC phase 2: mha1-3 K/V pairs
    {
        const float* kvsrc[3] = { his, cap, qry };
        const int    kvrows[3] = { BB*128, BB*64, BB*32 };
        for (int a = 0; a < 3; a++) {
            gemmN(sC, kvsrc[a], nullptr, 2,
                  AW(a+1,1), ABI(a+1,1), big2 + OFF_KV + (2*a)*1024*1024,
                  AW(a+1,2), ABI(a+1,2), big2 + OFF_KV + (2*a+1)*1024*1024,
                  nullptr, nullptr, kvrows[a], DD, DD, 0);
        }
        cudaEventRecord(eKV123, sC);
    }
    // sC phase 3: factored mha5/mha7 weight prep
    {
        gemmN(sC, AW(4,3), nullptr, 2, AW(5,1), nullptr, big3 + OFF_PK,
              AW(5,2), nullptr, big3 + OFF_PV, nullptr, nullptr, DD, DD, DD, 0);
        gemmN(sC, AW(6,3), nullptr, 2, AW(7,1), nullptr, big7 + OFF_PK,
              AW(7,2), nullptr, big7 + OFF_PV, nullptr, nullptr, DD, DD, DD, 0);
        bias_compose_kernel<<<64, 256, 0, sC>>>(ABI(4,3), AW(5,2), ABI(5,2), big3 + OFF_BV);
        bias_compose_kernel<<<64, 256, 0, sC>>>(ABI(6,3), AW(7,2), ABI(7,2), big7 + OFF_BV);
        build_bwk_kernel<<<(512*4096+255)/256, 256, 0, sC>>>(big3 + OFF_PK, big3 + OFF_BWK);
        build_bwv_kernel<<<(4096*512+255)/256, 256, 0, sC>>>(big3 + OFF_PV, big3 + OFF_BWV);
        build_bwk_kernel<<<(512*4096+255)/256, 256, 0, sC>>>(big7 + OFF_PK, big7 + OFF_BWK);
        build_bwv_kernel<<<(4096*512+255)/256, 256, 0, sC>>>(big7 + OFF_PV, big7 + OFF_BWV);
        cudaEventRecord(eC, sC);
    }

    // sA: maps
    build_maps_kernel<<<dim3(256, 3), 256, 0, sA>>>();
    cudaEventRecord(eMaps, sA);

    // sB: big vft projections
    cudaStreamWaitEvent(sB, eMaps, 0);
    gemmN(sB, vft, map_perm, 2, AW(4,1), ABI(4,1), big0, AW(4,2), ABI(4,2), big1,
          nullptr, nullptr, NTOK_VFT, DD, DD, 0);
    gemmN(sB, vft, nullptr, 2, AW(6,1), ABI(6,1), big4, AW(6,2), ABI(6,2), big5,
          nullptr, nullptr, NTOK_VFT, DD, DD, 0);
    cudaEventRecord(eVft, sB);

    // sA: mha0
    cudaStreamWaitEvent(sA, eQKV0, 0);
    attn(sA, qA, ks, vs, abA, BB, TTRG, 1, trg_m, 1, 1);
    gemm(sA, abA, nullptr, AW(0,3), ABI(0,3), x, nullptr, cur, NTOK_X, DD, DD, 0);

    // sA: mha1..3
    cudaStreamWaitEvent(sA, eKV123, 0);
    {
        const int  Lks[3]   = { 128, 64, 32 };
        const int* masks[3] = { his_m, cap_m, qry_m };
        for (int a = 0; a < 3; a++) {
            int wi = a + 1;
            ln(sA, cur, wi, lnA, NTOK_X);
            gemm(sA, lnA, nullptr, AW(wi,0), ABI(wi,0), nullptr, nullptr, qA, NTOK_X, DD, DD, 0);
            attn(sA, qA, big2 + OFF_KV + (2*a)*1024*1024, big2 + OFF_KV + (2*a+1)*1024*1024,
                 abA, BB, Lks[a], 1, masks[a], 2, 1);
            gemm(sA, abA, nullptr, AW(wi,3), ABI(wi,3), cur, nullptr, cur, NTOK_X, DD, DD, 0);
        }
    }
    cudaEventRecord(eCur, sA);

    // ========== chain A (sA) ==========
    ln(sA, cur, 4, lnA, NTOK_X);
    gemm(sA, lnA, nullptr, AW(4,0), ABI(4,0), nullptr, nullptr, qA, NTOK_X, DD, DD, 0);
    cudaStreamWaitEvent(sA, eVft, 0);
    attn(sA, qA, big0, big1, big2, BB*SS, TT, SS, tmp_m, 2, SS);
    ln(sA, cur, 5, lnA, NTOK_X);
    gemm(sA, lnA, nullptr, AW(5,0), ABI(5,0), nullptr, nullptr, qA, NTOK_X, DD, DD, 0);
    cudaStreamWaitEvent(sA, eC, 0);
    gemm(sA, cur, nullptr, AW(5,2), big3 + OFF_BV, nullptr, nullptr, big3 + OFF_U2,
         NTOK_X, DD, DD, 0);
    gemm(sA, qA, nullptr, big3 + OFF_BWK, nullptr, nullptr, nullptr, big3 + OFF_QT,
         NTOK_X, 4096, DD, 0);
    attn_wide_kernel<<<NTOK_X, 256, 0, sA>>>(big3 + OFF_QT, big2, map_pt, big3 + OFF_SB,
                                             SS, nullptr, 0, 1);
    gemm(sA, big3 + OFF_SB, nullptr, big3 + OFF_BWV, nullptr, big3 + OFF_U2, nullptr,
         abA, NTOK_X, DD, 4096, 0);
    gemm(sA, abA, nullptr, AW(5,3), ABI(5,3), cur, nullptr, ts, NTOK_X, DD, DD, 0);
    ln(sA, ts, 6, lnA, NTOK_X);
    gemm(sA, lnA, nullptr, ffw1 + 0*DD*DFF, ffb1 + 0*DFF, nullptr, nullptr, ffhA, NTOK_X, DFF, DD, 1);
    gemm(sA, ffhA, nullptr, ffw2 + 0*DFF*DD, ffb2 + 0*DD, ts, nullptr, ts, NTOK_X, DD, DFF, 0);

    // ========== chain B (sB) ==========
    cudaStreamWaitEvent(sB, eCur, 0);
    ln(sB, cur, 7, lnB, NTOK_X);
    gemm(sB, lnB, nullptr, AW(6,0), ABI(6,0), nullptr, nullptr, qB, NTOK_X, DD, DD, 0);
    attn(sB, qB, big4, big5, big6, BB*TT, SS, TT, nullptr, 0, 1);
    ln(sB, cur, 8, lnB, NTOK_X);
    gemm(sB, lnB, nullptr, AW(7,0), ABI(7,0), nullptr, nullptr, qB, NTOK_X, DD, DD, 0);
    cudaStreamWaitEvent(sB, eC, 0);
    gemm(sB, cur, nullptr, AW(7,2), big7 + OFF_BV, nullptr, nullptr, big7 + OFF_U2,
         NTOK_X, DD, DD, 0);
    gemm(sB, qB, nullptr, big7 + OFF_BWK, nullptr, nullptr, nullptr, big7 + OFF_QT,
         NTOK_X, 4096, DD, 0);
    attn_wide_kernel<<<NTOK_X, 256, 0, sB>>>(big7 + OFF_QT, big6, map_ps, big7 + OFF_SB,
                                             TT, tmp_m, 2, TTRG);
    gemm(sB, big7 + OFF_SB, nullptr, big7 + OFF_BWV, nullptr, big7 + OFF_U2, nullptr,
         abB, NTOK_X, DD, 4096, 0);
    gemm(sB, abB, nullptr, AW(7,3), ABI(7,3), cur, nullptr, st, NTOK_X, DD, DD, 0);
    ln(sB, st, 9, lnB, NTOK_X);
    gemm(sB, lnB, nullptr, ffw1 + 1*DD*DFF, ffb1 + 1*DFF, nullptr, nullptr, ffhB, NTOK_X, DFF, DD, 1);
    gemm(sB, ffhB, nullptr, ffw2 + 1*DFF*DD, ffb2 + 1*DD, st, nullptr, st, NTOK_X, DD, DFF, 0);
    cudaEventRecord(eB, sB);

    // ---- join on sA: fused add+LN, then ffn2 ----
    cudaStreamWaitEvent(sA, eB, 0);
    add_ln(sA, ts, st, cur, 10, lnA, NTOK_X);
    gemm(sA, lnA, nullptr, ffw1 + 2*DD*DFF, ffb1 + 2*DFF, nullptr, nullptr, ffhA, NTOK_X, DFF, DD, 1);
    gemm(sA, ffhA, nullptr, ffw2 + 2*DFF*DD, ffb2 + 2*DD, cur, nullptr, out, NTOK_X, DD, DFF, 0);

    cudaEventRecord(eEnd, sA);
    cudaStreamWaitEvent(0, eEnd, 0);

    #undef AW
    #undef ABI
}